// round 1
// baseline (speedup 1.0000x reference)
#include <cuda_runtime.h>
#include <math.h>

// Problem dims (fixed by the reference)
#define NB 2048   // batch
#define NI 256    // inner / contraction dim j
#define NO 256    // output dim i

// Scratch in __device__ globals (no allocations allowed).
// Stored j-major (transposed) so the hot loop loads are fully coalesced/vector.
__device__ __align__(16) float g_cxT[NI * NB];  // cos(phi0 + x[b,j])  at [j][b]
__device__ __align__(16) float g_sxT[NI * NB];  // sin(phi0 + x[b,j])  at [j][b]
__device__ __align__(16) float g_nco[NI * NO];  // -2*rho*cos(off[i,j]) at [j][i]
__device__ __align__(16) float g_so [NI * NO];  //  2*rho*sin(off[i,j]) at [j][i]

__global__ void prep_x_kernel(const float* __restrict__ x, float phi0) {
    int t = blockIdx.x * blockDim.x + threadIdx.x;   // t = j*NB + b
    if (t >= NB * NI) return;
    int j = t >> 11;          // / 2048
    int b = t & (NB - 1);
    float s, c;
    sincosf(phi0 + x[b * NI + j], &s, &c);
    g_cxT[t] = c;
    g_sxT[t] = s;
}

__global__ void prep_o_kernel(const float* __restrict__ off, float two_rho) {
    int t = blockIdx.x * blockDim.x + threadIdx.x;   // t = j*NO + i
    if (t >= NI * NO) return;
    int j = t >> 8;
    int i = t & (NO - 1);
    float s, c;
    sincosf(off[i * NI + j], &s, &c);
    g_nco[t] = -two_rho * c;
    g_so [t] =  two_rho * s;
}

__device__ __forceinline__ float frcp(float x) {
    float r;
    asm("rcp.approx.f32 %0, %1;" : "=f"(r) : "f"(x));
    return r;
}

// Main: each thread owns a 2(b) x 4(i) micro-tile; CTA tile = 32(b) x 64(i).
// Per element: d = fma(cx,nco, fma(sx,so,Q)); acc += rcp(d).  T = 1 - K/d exactly.
__global__ __launch_bounds__(256) void photonic_main(float* __restrict__ out,
                                                     float Qc, float negK) {
    const int tx = threadIdx.x & 15;          // 16 thread-groups along b
    const int ty = threadIdx.x >> 4;          // 16 thread-groups along i
    const int b0 = blockIdx.x * 32 + tx * 2;
    const int i0 = blockIdx.y * 64 + ty * 4;

    float a00 = 0.f, a01 = 0.f, a02 = 0.f, a03 = 0.f;
    float a10 = 0.f, a11 = 0.f, a12 = 0.f, a13 = 0.f;

    const float* cxp = g_cxT + b0;
    const float* sxp = g_sxT + b0;
    const float* ncp = g_nco + i0;
    const float* sop = g_so  + i0;

    #pragma unroll 4
    for (int j = 0; j < NI; ++j) {
        const float2 cx = *(const float2*)(cxp + j * NB);
        const float2 sx = *(const float2*)(sxp + j * NB);
        const float4 nc = *(const float4*)(ncp + j * NO);
        const float4 so = *(const float4*)(sop + j * NO);

        // row 0 (b0)
        a00 += frcp(fmaf(cx.x, nc.x, fmaf(sx.x, so.x, Qc)));
        a01 += frcp(fmaf(cx.x, nc.y, fmaf(sx.x, so.y, Qc)));
        a02 += frcp(fmaf(cx.x, nc.z, fmaf(sx.x, so.z, Qc)));
        a03 += frcp(fmaf(cx.x, nc.w, fmaf(sx.x, so.w, Qc)));
        // row 1 (b0+1)
        a10 += frcp(fmaf(cx.y, nc.x, fmaf(sx.y, so.x, Qc)));
        a11 += frcp(fmaf(cx.y, nc.y, fmaf(sx.y, so.y, Qc)));
        a12 += frcp(fmaf(cx.y, nc.z, fmaf(sx.y, so.z, Qc)));
        a13 += frcp(fmaf(cx.y, nc.w, fmaf(sx.y, so.w, Qc)));
    }

    // out[b,i] = NI - K * sum_j 1/d   (negK = -K)
    float4 r0, r1;
    r0.x = fmaf(negK, a00, (float)NI);
    r0.y = fmaf(negK, a01, (float)NI);
    r0.z = fmaf(negK, a02, (float)NI);
    r0.w = fmaf(negK, a03, (float)NI);
    r1.x = fmaf(negK, a10, (float)NI);
    r1.y = fmaf(negK, a11, (float)NI);
    r1.z = fmaf(negK, a12, (float)NI);
    r1.w = fmaf(negK, a13, (float)NI);

    *(float4*)(out + (b0 + 0) * NO + i0) = r0;
    *(float4*)(out + (b0 + 1) * NO + i0) = r1;
}

extern "C" void kernel_launch(void* const* d_in, const int* in_sizes, int n_in,
                              void* d_out, int out_size) {
    const float* x   = (const float*)d_in[0];   // input_matrix [2048, 256]
    const float* off = (const float*)d_in[1];   // phase_offset [256, 256]
    float* out = (float*)d_out;                 // [2048, 256]

    // Physics constants (double precision on host, passed as fp32)
    const double PI     = 3.14159265358979323846;
    const double RADIUS = 5e-6;
    const double KAPPA  = 0.1;
    const double N_EFF  = 3.48;
    const double LAMBDA = 1.55e-6;
    const double LOSS_A = 0.99;

    const double t   = sqrt(1.0 - KAPPA);
    const double a   = LOSS_A;
    const double rho = a * t;
    const double phi0 = fmod(2.0 * PI * N_EFF * (2.0 * PI * RADIUS) / LAMBDA, 2.0 * PI);

    const float Qc      = (float)(1.0 + rho * rho);
    const float two_rho = (float)(2.0 * rho);
    const float negK    = (float)(-(1.0 - t * t) * (1.0 - a * a));

    // Precompute trig tables (transposed layouts for the main loop)
    prep_x_kernel<<<(NB * NI + 255) / 256, 256>>>(x, (float)phi0);
    prep_o_kernel<<<(NI * NO + 255) / 256, 256>>>(off, two_rho);

    // Main compute: grid (2048/32, 256/64) = (64, 4) CTAs of 256 threads
    dim3 grid(NB / 32, NO / 64);
    photonic_main<<<grid, 256>>>(out, Qc, negK);
}

// round 2
// speedup vs baseline: 1.5265x; 1.5265x over previous
#include <cuda_runtime.h>
#include <math.h>

// Problem dims (fixed by the reference)
#define NB 2048   // batch
#define NI 256    // inner / contraction dim j
#define NO 256    // output dim i

// Scratch in __device__ globals (no allocations allowed).
// j-major (transposed) so hot-loop loads are coalesced / broadcast vectors.
__device__ __align__(16) float g_cxT[NI * NB];  // cos(phi0 + x[b,j])   at [j][b]
__device__ __align__(16) float g_sxT[NI * NB];  // sin(phi0 + x[b,j])   at [j][b]
__device__ __align__(16) float g_nco[NI * NO];  // -2*rho*cos(off[i,j]) at [j][i]
__device__ __align__(16) float g_so [NI * NO];  //  2*rho*sin(off[i,j]) at [j][i]

__global__ void prep_x_kernel(const float* __restrict__ x, float phi0) {
    int t = blockIdx.x * blockDim.x + threadIdx.x;   // t = j*NB + b
    if (t >= NB * NI) return;
    int j = t >> 11;          // / 2048
    int b = t & (NB - 1);
    float s, c;
    __sincosf(phi0 + x[b * NI + j], &s, &c);   // HW approx: |arg| < ~12, err ~1e-6
    g_cxT[t] = c;
    g_sxT[t] = s;
}

__global__ void prep_o_kernel(const float* __restrict__ off, float two_rho) {
    int t = blockIdx.x * blockDim.x + threadIdx.x;   // t = j*NO + i
    if (t >= NI * NO) return;
    int j = t >> 8;
    int i = t & (NO - 1);
    float s, c;
    __sincosf(off[i * NI + j], &s, &c);
    g_nco[t] = -two_rho * c;
    g_so [t] =  two_rho * s;
}

__device__ __forceinline__ float frcp(float x) {
    float r;
    asm("rcp.approx.f32 %0, %1;" : "=f"(r) : "f"(x));
    return r;
}

// T = 1 - K/d with d = Q - 2*rho*cos(phi).  Pairwise over j:
// 1/d0 + 1/d1 = (d0+d1) * rcp(d0*d1)   -> 0.5 MUFU / element.
#define CELL(acc, c0, s0, c1, s1, n0, o0, n1, o1)              \
    do {                                                       \
        float d0_ = fmaf((c0), (n0), fmaf((s0), (o0), Qc));    \
        float d1_ = fmaf((c1), (n1), fmaf((s1), (o1), Qc));    \
        (acc) = fmaf(d0_ + d1_, frcp(d0_ * d1_), (acc));       \
    } while (0)

// Each thread owns a 2(b) x 4(i) micro-tile; CTA tile = 32(b) x 64(i).
__global__ __launch_bounds__(256) void photonic_main(float* __restrict__ out,
                                                     float Qc, float negK) {
    const int tx = threadIdx.x & 15;          // 16 groups along b
    const int ty = threadIdx.x >> 4;          // 16 groups along i
    const int b0 = blockIdx.x * 32 + tx * 2;
    const int i0 = blockIdx.y * 64 + ty * 4;

    float a00 = 0.f, a01 = 0.f, a02 = 0.f, a03 = 0.f;
    float a10 = 0.f, a11 = 0.f, a12 = 0.f, a13 = 0.f;

    const float* cxp = g_cxT + b0;
    const float* sxp = g_sxT + b0;
    const float* ncp = g_nco + i0;
    const float* sop = g_so  + i0;

    #pragma unroll 4
    for (int j = 0; j < NI; j += 2) {
        // j and j+1 operands
        const float2 cx0 = *(const float2*)(cxp + (j    ) * NB);
        const float2 cx1 = *(const float2*)(cxp + (j + 1) * NB);
        const float2 sx0 = *(const float2*)(sxp + (j    ) * NB);
        const float2 sx1 = *(const float2*)(sxp + (j + 1) * NB);
        const float4 nc0 = *(const float4*)(ncp + (j    ) * NO);
        const float4 nc1 = *(const float4*)(ncp + (j + 1) * NO);
        const float4 so0 = *(const float4*)(sop + (j    ) * NO);
        const float4 so1 = *(const float4*)(sop + (j + 1) * NO);

        // row 0 (b0)
        CELL(a00, cx0.x, sx0.x, cx1.x, sx1.x, nc0.x, so0.x, nc1.x, so1.x);
        CELL(a01, cx0.x, sx0.x, cx1.x, sx1.x, nc0.y, so0.y, nc1.y, so1.y);
        CELL(a02, cx0.x, sx0.x, cx1.x, sx1.x, nc0.z, so0.z, nc1.z, so1.z);
        CELL(a03, cx0.x, sx0.x, cx1.x, sx1.x, nc0.w, so0.w, nc1.w, so1.w);
        // row 1 (b0+1)
        CELL(a10, cx0.y, sx0.y, cx1.y, sx1.y, nc0.x, so0.x, nc1.x, so1.x);
        CELL(a11, cx0.y, sx0.y, cx1.y, sx1.y, nc0.y, so0.y, nc1.y, so1.y);
        CELL(a12, cx0.y, sx0.y, cx1.y, sx1.y, nc0.z, so0.z, nc1.z, so1.z);
        CELL(a13, cx0.y, sx0.y, cx1.y, sx1.y, nc0.w, so0.w, nc1.w, so1.w);
    }

    // out[b,i] = NI - K * sum_j 1/d   (negK = -K)
    float4 r0, r1;
    r0.x = fmaf(negK, a00, (float)NI);
    r0.y = fmaf(negK, a01, (float)NI);
    r0.z = fmaf(negK, a02, (float)NI);
    r0.w = fmaf(negK, a03, (float)NI);
    r1.x = fmaf(negK, a10, (float)NI);
    r1.y = fmaf(negK, a11, (float)NI);
    r1.z = fmaf(negK, a12, (float)NI);
    r1.w = fmaf(negK, a13, (float)NI);

    *(float4*)(out + (b0 + 0) * NO + i0) = r0;
    *(float4*)(out + (b0 + 1) * NO + i0) = r1;
}

extern "C" void kernel_launch(void* const* d_in, const int* in_sizes, int n_in,
                              void* d_out, int out_size) {
    const float* x   = (const float*)d_in[0];   // input_matrix [2048, 256]
    const float* off = (const float*)d_in[1];   // phase_offset [256, 256]
    float* out = (float*)d_out;                 // [2048, 256]

    // Physics constants (double precision on host, passed as fp32)
    const double PI     = 3.14159265358979323846;
    const double RADIUS = 5e-6;
    const double KAPPA  = 0.1;
    const double N_EFF  = 3.48;
    const double LAMBDA = 1.55e-6;
    const double LOSS_A = 0.99;

    const double t   = sqrt(1.0 - KAPPA);
    const double a   = LOSS_A;
    const double rho = a * t;
    const double phi0 = fmod(2.0 * PI * N_EFF * (2.0 * PI * RADIUS) / LAMBDA, 2.0 * PI);

    const float Qc      = (float)(1.0 + rho * rho);
    const float two_rho = (float)(2.0 * rho);
    const float negK    = (float)(-(1.0 - t * t) * (1.0 - a * a));

    // Precompute trig tables (transposed layouts for the main loop)
    prep_x_kernel<<<(NB * NI + 255) / 256, 256>>>(x, (float)phi0);
    prep_o_kernel<<<(NI * NO + 255) / 256, 256>>>(off, two_rho);

    // Main compute: grid (2048/32, 256/64) = (64, 4) CTAs of 256 threads
    dim3 grid(NB / 32, NO / 64);
    photonic_main<<<grid, 256>>>(out, Qc, negK);
}

// round 3
// speedup vs baseline: 2.2101x; 1.4478x over previous
#include <cuda_runtime.h>
#include <math.h>

// Problem dims (fixed by the reference)
#define NB 2048   // batch
#define NI 256    // inner / contraction dim j
#define NO 256    // output dim i

typedef unsigned long long ull;

// Pair-interleaved trig tables: for pair index j2 = j/2,
//   g_cx2[(j2*NB + b)*2 + 0] = cos(phi0 + x[b, 2*j2])
//   g_cx2[(j2*NB + b)*2 + 1] = cos(phi0 + x[b, 2*j2+1])
// so one 64-bit load yields the f32x2 operand pair for (j, j+1).
__device__ __align__(16) float g_cx2[NI * NB];
__device__ __align__(16) float g_sx2[NI * NB];
__device__ __align__(16) float g_nc2[NI * NO];  // -2*rho*cos(off)
__device__ __align__(16) float g_so2[NI * NO];  //  2*rho*sin(off)

// ---------------- prep: smem tile transpose + __sincosf ----------------
// Input  src is [R, NI] row-major (rows = b or i).
// Output pair-interleaved j-major tables (row index fastest, stride 2).
template <int R_TOTAL>
__global__ void prep_kernel(const float* __restrict__ src,
                            float* __restrict__ dst_c, float* __restrict__ dst_s,
                            float add_phase, float mul_c, float mul_s) {
    __shared__ float tile[32][33];
    const int r0 = blockIdx.x * 32;   // row-block (b or i)
    const int j0 = blockIdx.y * 32;   // j-block
    const int lane = threadIdx.x & 31;
    const int row4 = threadIdx.x >> 5;   // 0..7

    // coalesced read: 32 rows x 32 j
    #pragma unroll
    for (int rr = 0; rr < 4; ++rr) {
        int r = row4 + rr * 8;
        tile[r][lane] = src[(r0 + r) * NI + j0 + lane];
    }
    __syncthreads();

    // write: jj slow, row fast (stride-2 interleave by j parity)
    #pragma unroll
    for (int k = 0; k < 4; ++k) {
        int jj = row4 + k * 8;          // 0..31
        int rowi = lane;                // 0..31
        float s, c;
        __sincosf(add_phase + tile[rowi][jj], &s, &c);
        int idx = (((j0 + jj) >> 1) * R_TOTAL + (r0 + rowi)) * 2 + (jj & 1);
        dst_c[idx] = mul_c * c;
        dst_s[idx] = mul_s * s;
    }
}

// ---------------- packed f32x2 helpers ----------------
__device__ __forceinline__ ull ffma2(ull a, ull b, ull c) {
    ull d;
    asm("fma.rn.f32x2 %0, %1, %2, %3;" : "=l"(d) : "l"(a), "l"(b), "l"(c));
    return d;
}
__device__ __forceinline__ ull fadd2(ull a, ull b) {
    ull d;
    asm("add.rn.f32x2 %0, %1, %2;" : "=l"(d) : "l"(a), "l"(b));
    return d;
}
__device__ __forceinline__ ull fmul2(ull a, ull b) {
    ull d;
    asm("mul.rn.f32x2 %0, %1, %2;" : "=l"(d) : "l"(a), "l"(b));
    return d;
}
__device__ __forceinline__ float2 u2f(ull v) {
    float2 r;
    asm("mov.b64 {%0, %1}, %2;" : "=f"(r.x), "=f"(r.y) : "l"(v));
    return r;
}
__device__ __forceinline__ float frcp(float x) {
    float r;
    asm("rcp.approx.f32 %0, %1;" : "=f"(r) : "f"(x));
    return r;
}

// 4 j-terms fused: D=(d_j0,d_j1), E=(d_j2,d_j3).
// sum 1/d = S.x/P.x + S.y/P.y with S=D+E, P=D*E (cross-pairing (j0,j2),(j1,j3)).
#define QCELL(acc, cA, sA, cB, sB, nA, oA, nB, oB)                     \
    do {                                                               \
        ull D_ = ffma2((cA), (nA), ffma2((sA), (oA), Q2));             \
        ull E_ = ffma2((cB), (nB), ffma2((sB), (oB), Q2));             \
        float2 S_ = u2f(fadd2(D_, E_));                                \
        float2 P_ = u2f(fmul2(D_, E_));                                \
        (acc) = fmaf(fmaf(S_.x, P_.y, S_.y * P_.x),                    \
                     frcp(P_.x * P_.y), (acc));                        \
    } while (0)

// Each thread: 2(b) x 4(i) micro-tile; CTA tile = 32(b) x 64(i).
__global__ __launch_bounds__(256) void photonic_main(float* __restrict__ out,
                                                     ull Q2, float negK) {
    const int tx = threadIdx.x & 15;
    const int ty = threadIdx.x >> 4;
    const int b0 = blockIdx.x * 32 + tx * 2;   // even
    const int i0 = blockIdx.y * 64 + ty * 4;   // mult of 4

    float a00 = 0.f, a01 = 0.f, a02 = 0.f, a03 = 0.f;
    float a10 = 0.f, a11 = 0.f, a12 = 0.f, a13 = 0.f;

    // ulonglong2 covers two adjacent (b) or (i) pair-entries
    const ulonglong2* cxp = ((const ulonglong2*)g_cx2) + (b0 >> 1);
    const ulonglong2* sxp = ((const ulonglong2*)g_sx2) + (b0 >> 1);
    const ulonglong2* ncp = ((const ulonglong2*)g_nc2) + (i0 >> 1);
    const ulonglong2* sop = ((const ulonglong2*)g_so2) + (i0 >> 1);

    #pragma unroll 2
    for (int j2 = 0; j2 < NI / 2; j2 += 2) {     // two j-pairs (4 j) per iter
        const ulonglong2 cxA = cxp[(j2    ) * (NB / 2)];
        const ulonglong2 cxB = cxp[(j2 + 1) * (NB / 2)];
        const ulonglong2 sxA = sxp[(j2    ) * (NB / 2)];
        const ulonglong2 sxB = sxp[(j2 + 1) * (NB / 2)];
        const ulonglong2 ncA0 = ncp[(j2    ) * (NO / 2)];
        const ulonglong2 ncA1 = ncp[(j2    ) * (NO / 2) + 1];
        const ulonglong2 ncB0 = ncp[(j2 + 1) * (NO / 2)];
        const ulonglong2 ncB1 = ncp[(j2 + 1) * (NO / 2) + 1];
        const ulonglong2 soA0 = sop[(j2    ) * (NO / 2)];
        const ulonglong2 soA1 = sop[(j2    ) * (NO / 2) + 1];
        const ulonglong2 soB0 = sop[(j2 + 1) * (NO / 2)];
        const ulonglong2 soB1 = sop[(j2 + 1) * (NO / 2) + 1];

        // row 0 (b0)
        QCELL(a00, cxA.x, sxA.x, cxB.x, sxB.x, ncA0.x, soA0.x, ncB0.x, soB0.x);
        QCELL(a01, cxA.x, sxA.x, cxB.x, sxB.x, ncA0.y, soA0.y, ncB0.y, soB0.y);
        QCELL(a02, cxA.x, sxA.x, cxB.x, sxB.x, ncA1.x, soA1.x, ncB1.x, soB1.x);
        QCELL(a03, cxA.x, sxA.x, cxB.x, sxB.x, ncA1.y, soA1.y, ncB1.y, soB1.y);
        // row 1 (b0+1)
        QCELL(a10, cxA.y, sxA.y, cxB.y, sxB.y, ncA0.x, soA0.x, ncB0.x, soB0.x);
        QCELL(a11, cxA.y, sxA.y, cxB.y, sxB.y, ncA0.y, soA0.y, ncB0.y, soB0.y);
        QCELL(a12, cxA.y, sxA.y, cxB.y, sxB.y, ncA1.x, soA1.x, ncB1.x, soB1.x);
        QCELL(a13, cxA.y, sxA.y, cxB.y, sxB.y, ncA1.y, soA1.y, ncB1.y, soB1.y);
    }

    float4 r0, r1;
    r0.x = fmaf(negK, a00, (float)NI);
    r0.y = fmaf(negK, a01, (float)NI);
    r0.z = fmaf(negK, a02, (float)NI);
    r0.w = fmaf(negK, a03, (float)NI);
    r1.x = fmaf(negK, a10, (float)NI);
    r1.y = fmaf(negK, a11, (float)NI);
    r1.z = fmaf(negK, a12, (float)NI);
    r1.w = fmaf(negK, a13, (float)NI);

    *(float4*)(out + (b0 + 0) * NO + i0) = r0;
    *(float4*)(out + (b0 + 1) * NO + i0) = r1;
}

extern "C" void kernel_launch(void* const* d_in, const int* in_sizes, int n_in,
                              void* d_out, int out_size) {
    const float* x   = (const float*)d_in[0];   // input_matrix [2048, 256]
    const float* off = (const float*)d_in[1];   // phase_offset [256, 256]
    float* out = (float*)d_out;                 // [2048, 256]

    // Physics constants
    const double PI     = 3.14159265358979323846;
    const double RADIUS = 5e-6;
    const double KAPPA  = 0.1;
    const double N_EFF  = 3.48;
    const double LAMBDA = 1.55e-6;
    const double LOSS_A = 0.99;

    const double t   = sqrt(1.0 - KAPPA);
    const double a   = LOSS_A;
    const double rho = a * t;
    const double phi0 = fmod(2.0 * PI * N_EFF * (2.0 * PI * RADIUS) / LAMBDA, 2.0 * PI);

    const float Qc      = (float)(1.0 + rho * rho);
    const float two_rho = (float)(2.0 * rho);
    const float negK    = (float)(-(1.0 - t * t) * (1.0 - a * a));

    unsigned int qbits;
    memcpy(&qbits, &Qc, 4);
    const ull Q2 = ((ull)qbits << 32) | qbits;   // packed (Qc, Qc)

    float *g_cx2_p, *g_sx2_p, *g_nc2_p, *g_so2_p;
    cudaGetSymbolAddress((void**)&g_cx2_p, g_cx2);
    cudaGetSymbolAddress((void**)&g_sx2_p, g_sx2);
    cudaGetSymbolAddress((void**)&g_nc2_p, g_nc2);
    cudaGetSymbolAddress((void**)&g_so2_p, g_so2);

    // prep: x table (2048 rows) and offset table (256 rows)
    prep_kernel<NB><<<dim3(NB / 32, NI / 32), 256>>>(x, g_cx2_p, g_sx2_p,
                                                     (float)phi0, 1.0f, 1.0f);
    prep_kernel<NO><<<dim3(NO / 32, NI / 32), 256>>>(off, g_nc2_p, g_so2_p,
                                                     0.0f, -two_rho, two_rho);

    // main: grid (2048/32, 256/64) = (64, 4) CTAs of 256 threads
    dim3 grid(NB / 32, NO / 64);
    photonic_main<<<grid, 256>>>(out, Q2, negK);
}

// round 4
// speedup vs baseline: 2.7684x; 1.2526x over previous
#include <cuda_runtime.h>
#include <math.h>

// Problem dims (fixed by the reference)
#define NB 2048   // batch
#define NI 256    // inner / contraction dim j
#define NO 256    // output dim i

#define J_CH   64                 // j-chunk per smem stage
#define CX_STRIDE 68              // floats per j-pair row (64 + 4 pad), x-side
#define NC_STRIDE 132             // floats per j-pair row (128 + 4 pad), o-side
#define CX_ELEMS ((J_CH / 2) * CX_STRIDE)   // 2176 floats
#define NC_ELEMS ((J_CH / 2) * NC_STRIDE)   // 4224 floats
#define SMEM_FLOATS (2 * CX_ELEMS + 2 * NC_ELEMS)   // 12800 -> 51200 B

typedef unsigned long long ull;

// ---------------- packed f32x2 helpers ----------------
__device__ __forceinline__ ull ffma2(ull a, ull b, ull c) {
    ull d;
    asm("fma.rn.f32x2 %0, %1, %2, %3;" : "=l"(d) : "l"(a), "l"(b), "l"(c));
    return d;
}
__device__ __forceinline__ ull fadd2(ull a, ull b) {
    ull d;
    asm("add.rn.f32x2 %0, %1, %2;" : "=l"(d) : "l"(a), "l"(b));
    return d;
}
__device__ __forceinline__ ull fmul2(ull a, ull b) {
    ull d;
    asm("mul.rn.f32x2 %0, %1, %2;" : "=l"(d) : "l"(a), "l"(b));
    return d;
}
__device__ __forceinline__ float2 u2f(ull v) {
    float2 r;
    asm("mov.b64 {%0, %1}, %2;" : "=f"(r.x), "=f"(r.y) : "l"(v));
    return r;
}
__device__ __forceinline__ float frcp(float x) {
    float r;
    asm("rcp.approx.f32 %0, %1;" : "=f"(r) : "f"(x));
    return r;
}

// 4 j-terms fused: D=(d_j0,d_j1), E=(d_j2,d_j3).
// sum 1/d = (S.x*P.y + S.y*P.x) * rcp(P.x*P.y), S=D+E, P=D*E.
#define QCELL(acc, cA, sA, cB, sB, nA, oA, nB, oB)                     \
    do {                                                               \
        ull D_ = ffma2((cA), (nA), ffma2((sA), (oA), Q2));             \
        ull E_ = ffma2((cB), (nB), ffma2((sB), (oB), Q2));             \
        float2 S_ = u2f(fadd2(D_, E_));                                \
        float2 P_ = u2f(fmul2(D_, E_));                                \
        (acc) = fmaf(fmaf(S_.x, P_.y, S_.y * P_.x),                    \
                     frcp(P_.x * P_.y), (acc));                        \
    } while (0)

// Single fused kernel. CTA tile = 32(b) x 64(i); thread micro-tile 2(b) x 4(i).
// Trig tables built per-CTA in smem, j-chunked (J_CH=64, 4 chunks).
__global__ __launch_bounds__(256) void photonic_fused(
        float* __restrict__ out,
        const float* __restrict__ x, const float* __restrict__ off,
        float phi0, float two_rho, ull Q2, float negK) {
    extern __shared__ float smem[];
    float* s_cx = smem;                         // [J_CH/2][CX_STRIDE]
    float* s_sx = s_cx + CX_ELEMS;
    float* s_nc = s_sx + CX_ELEMS;              // [J_CH/2][NC_STRIDE]
    float* s_so = s_nc + NC_ELEMS;

    const int t  = threadIdx.x;
    const int tx = t & 15;                      // 16 groups along b
    const int ty = t >> 4;                      // 16 groups along i
    const int b_blk = blockIdx.x * 32;
    const int i_blk = blockIdx.y * 64;

    // fill-phase coordinates
    const int jj  = t & 63;                     // j within chunk
    const int g4  = t >> 6;                     // 0..3
    const int par = jj & 1;
    const int jph = jj >> 1;                    // j-pair row

    float a00 = 0.f, a01 = 0.f, a02 = 0.f, a03 = 0.f;
    float a10 = 0.f, a11 = 0.f, a12 = 0.f, a13 = 0.f;

    for (int chunk = 0; chunk < NI / J_CH; ++chunk) {
        const int j_base = chunk * J_CH;
        __syncthreads();   // previous chunk's reads done before overwrite

        // x-side: 32 rows x 64 j  (8 sincos / thread), coalesced gmem reads
        #pragma unroll
        for (int k = 0; k < 8; ++k) {
            int bl = g4 + k * 4;
            float s, c;
            __sincosf(phi0 + x[(b_blk + bl) * NI + j_base + jj], &s, &c);
            int idx = jph * CX_STRIDE + bl * 2 + par;
            s_cx[idx] = c;
            s_sx[idx] = s;
        }
        // o-side: 64 rows x 64 j  (16 sincos / thread)
        #pragma unroll
        for (int k = 0; k < 16; ++k) {
            int il = g4 + k * 4;
            float s, c;
            __sincosf(off[(i_blk + il) * NI + j_base + jj], &s, &c);
            int idx = jph * NC_STRIDE + il * 2 + par;
            s_nc[idx] = -two_rho * c;
            s_so[idx] =  two_rho * s;
        }
        __syncthreads();

        const float* cxb = s_cx + tx * 4;       // this thread's 2 b's (pair-interleaved)
        const float* sxb = s_sx + tx * 4;
        const float* ncb = s_nc + ty * 8;       // this thread's 4 i's
        const float* sob = s_so + ty * 8;

        #pragma unroll 2
        for (int jp = 0; jp < J_CH / 2; jp += 2) {   // 4 j per iter
            const ulonglong2 cxA = *(const ulonglong2*)(cxb + (jp    ) * CX_STRIDE);
            const ulonglong2 cxB = *(const ulonglong2*)(cxb + (jp + 1) * CX_STRIDE);
            const ulonglong2 sxA = *(const ulonglong2*)(sxb + (jp    ) * CX_STRIDE);
            const ulonglong2 sxB = *(const ulonglong2*)(sxb + (jp + 1) * CX_STRIDE);
            const ulonglong2 nA  = *(const ulonglong2*)(ncb + (jp    ) * NC_STRIDE);
            const ulonglong2 nA1 = *(const ulonglong2*)(ncb + (jp    ) * NC_STRIDE + 4);
            const ulonglong2 nB  = *(const ulonglong2*)(ncb + (jp + 1) * NC_STRIDE);
            const ulonglong2 nB1 = *(const ulonglong2*)(ncb + (jp + 1) * NC_STRIDE + 4);
            const ulonglong2 oA  = *(const ulonglong2*)(sob + (jp    ) * NC_STRIDE);
            const ulonglong2 oA1 = *(const ulonglong2*)(sob + (jp    ) * NC_STRIDE + 4);
            const ulonglong2 oB  = *(const ulonglong2*)(sob + (jp + 1) * NC_STRIDE);
            const ulonglong2 oB1 = *(const ulonglong2*)(sob + (jp + 1) * NC_STRIDE + 4);

            // row 0 (b0)
            QCELL(a00, cxA.x, sxA.x, cxB.x, sxB.x, nA.x,  oA.x,  nB.x,  oB.x);
            QCELL(a01, cxA.x, sxA.x, cxB.x, sxB.x, nA.y,  oA.y,  nB.y,  oB.y);
            QCELL(a02, cxA.x, sxA.x, cxB.x, sxB.x, nA1.x, oA1.x, nB1.x, oB1.x);
            QCELL(a03, cxA.x, sxA.x, cxB.x, sxB.x, nA1.y, oA1.y, nB1.y, oB1.y);
            // row 1 (b0+1)
            QCELL(a10, cxA.y, sxA.y, cxB.y, sxB.y, nA.x,  oA.x,  nB.x,  oB.x);
            QCELL(a11, cxA.y, sxA.y, cxB.y, sxB.y, nA.y,  oA.y,  nB.y,  oB.y);
            QCELL(a12, cxA.y, sxA.y, cxB.y, sxB.y, nA1.x, oA1.x, nB1.x, oB1.x);
            QCELL(a13, cxA.y, sxA.y, cxB.y, sxB.y, nA1.y, oA1.y, nB1.y, oB1.y);
        }
    }

    const int b0 = b_blk + tx * 2;
    const int i0 = i_blk + ty * 4;
    float4 r0, r1;
    r0.x = fmaf(negK, a00, (float)NI);
    r0.y = fmaf(negK, a01, (float)NI);
    r0.z = fmaf(negK, a02, (float)NI);
    r0.w = fmaf(negK, a03, (float)NI);
    r1.x = fmaf(negK, a10, (float)NI);
    r1.y = fmaf(negK, a11, (float)NI);
    r1.z = fmaf(negK, a12, (float)NI);
    r1.w = fmaf(negK, a13, (float)NI);
    *(float4*)(out + (b0 + 0) * NO + i0) = r0;
    *(float4*)(out + (b0 + 1) * NO + i0) = r1;
}

extern "C" void kernel_launch(void* const* d_in, const int* in_sizes, int n_in,
                              void* d_out, int out_size) {
    const float* x   = (const float*)d_in[0];   // input_matrix [2048, 256]
    const float* off = (const float*)d_in[1];   // phase_offset [256, 256]
    float* out = (float*)d_out;                 // [2048, 256]

    // Physics constants
    const double PI     = 3.14159265358979323846;
    const double RADIUS = 5e-6;
    const double KAPPA  = 0.1;
    const double N_EFF  = 3.48;
    const double LAMBDA = 1.55e-6;
    const double LOSS_A = 0.99;

    const double t   = sqrt(1.0 - KAPPA);
    const double a   = LOSS_A;
    const double rho = a * t;
    const double phi0 = fmod(2.0 * PI * N_EFF * (2.0 * PI * RADIUS) / LAMBDA, 2.0 * PI);

    const float Qc      = (float)(1.0 + rho * rho);
    const float two_rho = (float)(2.0 * rho);
    const float negK    = (float)(-(1.0 - t * t) * (1.0 - a * a));

    unsigned int qbits;
    memcpy(&qbits, &Qc, 4);
    const ull Q2 = ((ull)qbits << 32) | qbits;   // packed (Qc, Qc)

    const int smem_bytes = SMEM_FLOATS * sizeof(float);   // 51200
    cudaFuncSetAttribute(photonic_fused,
                         cudaFuncAttributeMaxDynamicSharedMemorySize, smem_bytes);

    dim3 grid(NB / 32, NO / 64);   // (64, 4)
    photonic_fused<<<grid, 256, smem_bytes>>>(out, x, off,
                                              (float)phi0, two_rho, Q2, negK);
}

// round 5
// speedup vs baseline: 2.7864x; 1.0065x over previous
#include <cuda_runtime.h>
#include <math.h>

// Problem dims (fixed by the reference)
#define NB 2048   // batch
#define NI 256    // inner / contraction dim j
#define NO 256    // output dim i

#define J_CH 64                   // j-chunk per smem stage
#define CX_STRIDE 68              // floats per j-pair row (32b * 2 + 4 pad)
#define NC_STRIDE 68              // floats per j-pair row (32i * 2 + 4 pad)
#define CX_ELEMS ((J_CH / 2) * CX_STRIDE)   // 2176 floats
#define NC_ELEMS ((J_CH / 2) * NC_STRIDE)   // 2176 floats
#define SMEM_FLOATS (2 * CX_ELEMS + 2 * NC_ELEMS)   // 8704 -> 34816 B

typedef unsigned long long ull;

// ---------------- packed f32x2 helpers ----------------
__device__ __forceinline__ ull ffma2(ull a, ull b, ull c) {
    ull d;
    asm("fma.rn.f32x2 %0, %1, %2, %3;" : "=l"(d) : "l"(a), "l"(b), "l"(c));
    return d;
}
__device__ __forceinline__ ull fadd2(ull a, ull b) {
    ull d;
    asm("add.rn.f32x2 %0, %1, %2;" : "=l"(d) : "l"(a), "l"(b));
    return d;
}
__device__ __forceinline__ ull fmul2(ull a, ull b) {
    ull d;
    asm("mul.rn.f32x2 %0, %1, %2;" : "=l"(d) : "l"(a), "l"(b));
    return d;
}
__device__ __forceinline__ float2 u2f(ull v) {
    float2 r;
    asm("mov.b64 {%0, %1}, %2;" : "=f"(r.x), "=f"(r.y) : "l"(v));
    return r;
}
__device__ __forceinline__ float frcp(float x) {
    float r;
    asm("rcp.approx.f32 %0, %1;" : "=f"(r) : "f"(x));
    return r;
}

// 4 j-terms fused: D=(d_j0,d_j1), E=(d_j2,d_j3).
// sum 1/d = (S.x*P.y + S.y*P.x) * rcp(P.x*P.y), S=D+E, P=D*E.
#define QCELL(acc, cA, sA, cB, sB, nA, oA, nB, oB)                     \
    do {                                                               \
        ull D_ = ffma2((cA), (nA), ffma2((sA), (oA), Q2));             \
        ull E_ = ffma2((cB), (nB), ffma2((sB), (oB), Q2));             \
        float2 S_ = u2f(fadd2(D_, E_));                                \
        float2 P_ = u2f(fmul2(D_, E_));                                \
        (acc) = fmaf(fmaf(S_.x, P_.y, S_.y * P_.x),                    \
                     frcp(P_.x * P_.y), (acc));                        \
    } while (0)

// CTA tile = 32(b) x 32(i), 128 threads, thread micro-tile 2(b) x 4(i).
// grid (64, 8) = 512 CTAs -> 3-4 resident waves-worth of CTAs per SM.
__global__ __launch_bounds__(128, 6) void photonic_fused(
        float* __restrict__ out,
        const float* __restrict__ x, const float* __restrict__ off,
        float phi0, float two_rho, ull Q2, float negK) {
    extern __shared__ float smem[];
    float* s_cx = smem;                         // [J_CH/2][CX_STRIDE]
    float* s_sx = s_cx + CX_ELEMS;
    float* s_nc = s_sx + CX_ELEMS;              // [J_CH/2][NC_STRIDE]
    float* s_so = s_nc + NC_ELEMS;

    const int t  = threadIdx.x;
    const int tx = t & 15;                      // 16 groups along b
    const int ty = t >> 4;                      // 8 groups along i
    const int b_blk = blockIdx.x * 32;
    const int i_blk = blockIdx.y * 32;

    // fill-phase coordinates
    const int jj  = t & 63;                     // j within chunk
    const int g2  = t >> 6;                     // 0..1
    const int par = jj & 1;
    const int jph = jj >> 1;                    // j-pair row

    float a00 = 0.f, a01 = 0.f, a02 = 0.f, a03 = 0.f;
    float a10 = 0.f, a11 = 0.f, a12 = 0.f, a13 = 0.f;

    for (int chunk = 0; chunk < NI / J_CH; ++chunk) {
        const int j_base = chunk * J_CH;
        __syncthreads();   // previous chunk's reads done before overwrite

        // x-side: 32 rows x 64 j  (16 sincos / thread), coalesced gmem reads
        #pragma unroll
        for (int k = 0; k < 16; ++k) {
            int bl = g2 + k * 2;
            float s, c;
            __sincosf(phi0 + x[(b_blk + bl) * NI + j_base + jj], &s, &c);
            int idx = jph * CX_STRIDE + bl * 2 + par;
            s_cx[idx] = c;
            s_sx[idx] = s;
        }
        // o-side: 32 rows x 64 j  (16 sincos / thread)
        #pragma unroll
        for (int k = 0; k < 16; ++k) {
            int il = g2 + k * 2;
            float s, c;
            __sincosf(off[(i_blk + il) * NI + j_base + jj], &s, &c);
            int idx = jph * NC_STRIDE + il * 2 + par;
            s_nc[idx] = -two_rho * c;
            s_so[idx] =  two_rho * s;
        }
        __syncthreads();

        const float* cxb = s_cx + tx * 4;       // this thread's 2 b's (pair-interleaved)
        const float* sxb = s_sx + tx * 4;
        const float* ncb = s_nc + ty * 8;       // this thread's 4 i's
        const float* sob = s_so + ty * 8;

        #pragma unroll 4
        for (int jp = 0; jp < J_CH / 2; jp += 2) {   // 4 j per iter
            const ulonglong2 cxA = *(const ulonglong2*)(cxb + (jp    ) * CX_STRIDE);
            const ulonglong2 cxB = *(const ulonglong2*)(cxb + (jp + 1) * CX_STRIDE);
            const ulonglong2 sxA = *(const ulonglong2*)(sxb + (jp    ) * CX_STRIDE);
            const ulonglong2 sxB = *(const ulonglong2*)(sxb + (jp + 1) * CX_STRIDE);
            const ulonglong2 nA  = *(const ulonglong2*)(ncb + (jp    ) * NC_STRIDE);
            const ulonglong2 nA1 = *(const ulonglong2*)(ncb + (jp    ) * NC_STRIDE + 4);
            const ulonglong2 nB  = *(const ulonglong2*)(ncb + (jp + 1) * NC_STRIDE);
            const ulonglong2 nB1 = *(const ulonglong2*)(ncb + (jp + 1) * NC_STRIDE + 4);
            const ulonglong2 oA  = *(const ulonglong2*)(sob + (jp    ) * NC_STRIDE);
            const ulonglong2 oA1 = *(const ulonglong2*)(sob + (jp    ) * NC_STRIDE + 4);
            const ulonglong2 oB  = *(const ulonglong2*)(sob + (jp + 1) * NC_STRIDE);
            const ulonglong2 oB1 = *(const ulonglong2*)(sob + (jp + 1) * NC_STRIDE + 4);

            // row 0 (b0)
            QCELL(a00, cxA.x, sxA.x, cxB.x, sxB.x, nA.x,  oA.x,  nB.x,  oB.x);
            QCELL(a01, cxA.x, sxA.x, cxB.x, sxB.x, nA.y,  oA.y,  nB.y,  oB.y);
            QCELL(a02, cxA.x, sxA.x, cxB.x, sxB.x, nA1.x, oA1.x, nB1.x, oB1.x);
            QCELL(a03, cxA.x, sxA.x, cxB.x, sxB.x, nA1.y, oA1.y, nB1.y, oB1.y);
            // row 1 (b0+1)
            QCELL(a10, cxA.y, sxA.y, cxB.y, sxB.y, nA.x,  oA.x,  nB.x,  oB.x);
            QCELL(a11, cxA.y, sxA.y, cxB.y, sxB.y, nA.y,  oA.y,  nB.y,  oB.y);
            QCELL(a12, cxA.y, sxA.y, cxB.y, sxB.y, nA1.x, oA1.x, nB1.x, oB1.x);
            QCELL(a13, cxA.y, sxA.y, cxB.y, sxB.y, nA1.y, oA1.y, nB1.y, oB1.y);
        }
    }

    const int b0 = b_blk + tx * 2;
    const int i0 = i_blk + ty * 4;
    float4 r0, r1;
    r0.x = fmaf(negK, a00, (float)NI);
    r0.y = fmaf(negK, a01, (float)NI);
    r0.z = fmaf(negK, a02, (float)NI);
    r0.w = fmaf(negK, a03, (float)NI);
    r1.x = fmaf(negK, a10, (float)NI);
    r1.y = fmaf(negK, a11, (float)NI);
    r1.z = fmaf(negK, a12, (float)NI);
    r1.w = fmaf(negK, a13, (float)NI);
    *(float4*)(out + (b0 + 0) * NO + i0) = r0;
    *(float4*)(out + (b0 + 1) * NO + i0) = r1;
}

extern "C" void kernel_launch(void* const* d_in, const int* in_sizes, int n_in,
                              void* d_out, int out_size) {
    const float* x   = (const float*)d_in[0];   // input_matrix [2048, 256]
    const float* off = (const float*)d_in[1];   // phase_offset [256, 256]
    float* out = (float*)d_out;                 // [2048, 256]

    // Physics constants
    const double PI     = 3.14159265358979323846;
    const double RADIUS = 5e-6;
    const double KAPPA  = 0.1;
    const double N_EFF  = 3.48;
    const double LAMBDA = 1.55e-6;
    const double LOSS_A = 0.99;

    const double t   = sqrt(1.0 - KAPPA);
    const double a   = LOSS_A;
    const double rho = a * t;
    const double phi0 = fmod(2.0 * PI * N_EFF * (2.0 * PI * RADIUS) / LAMBDA, 2.0 * PI);

    const float Qc      = (float)(1.0 + rho * rho);
    const float two_rho = (float)(2.0 * rho);
    const float negK    = (float)(-(1.0 - t * t) * (1.0 - a * a));

    unsigned int qbits;
    memcpy(&qbits, &Qc, 4);
    const ull Q2 = ((ull)qbits << 32) | qbits;   // packed (Qc, Qc)

    const int smem_bytes = SMEM_FLOATS * sizeof(float);   // 34816
    cudaFuncSetAttribute(photonic_fused,
                         cudaFuncAttributeMaxDynamicSharedMemorySize, smem_bytes);

    dim3 grid(NB / 32, NO / 32);   // (64, 8) = 512 CTAs
    photonic_fused<<<grid, 128, smem_bytes>>>(out, x, off,
                                              (float)phi0, two_rho, Q2, negK);
}